// round 1
// baseline (speedup 1.0000x reference)
#include <cuda_runtime.h>
#include <math.h>

// ---------------------------------------------------------------------------
// MEGA (Moving-average Gated Attention) forward, fp32 baseline.
// L=2048 B=8 D=1024 Z=128 H=2048 N_ema=16, out (L,B,D) f32.
// ---------------------------------------------------------------------------

#define LSEQ   2048
#define BATCH  8
#define DDIM   1024
#define ZDIM   128
#define HDIM   2048
#define NEMA   16
#define MAXPOS 2048
#define DOUT   (ZDIM + HDIM + 2 * DDIM)   // 4224

// ------------------------- scratch (device globals) ------------------------
__device__ float g_xn [LSEQ * BATCH * DDIM];      // layernorm(x)       (l,b,d)
__device__ float g_mx [LSEQ * BATCH * DDIM];      // silu(ema conv)     (l,b,d)
__device__ float g_u  [LSEQ * BATCH * DDIM];      // gate u             (l,b,d)
__device__ float g_hx [LSEQ * BATCH * DDIM];      // hx                 (l,b,d)
__device__ float g_v  [BATCH * LSEQ * HDIM];      // value              (b,l,h)
__device__ float g_r  [BATCH * LSEQ * HDIM];      // r gate             (b,l,h)
__device__ float g_h  [BATCH * LSEQ * HDIM];      // (attn@v)*r         (b,l,h)
__device__ float g_qm [BATCH * LSEQ * ZDIM];      // q                  (b,l,z)
__device__ float g_kT [BATCH * ZDIM * LSEQ];      // k transposed       (b,z,l)
__device__ float g_attn[(size_t)BATCH * LSEQ * LSEQ]; // laplace scores (b,l,m)
__device__ float g_wn [DDIM * NEMA];              // ema output weights
__device__ float g_qn [DDIM * NEMA];              // ema decay factors

// ------------------------------- helpers -----------------------------------
__device__ __forceinline__ float sigmoidf_(float x) { return 1.f / (1.f + __expf(-x)); }
__device__ __forceinline__ float siluf_(float x)    { return x / (1.f + __expf(-x)); }
__device__ __forceinline__ float laplacef_(float x) {
    // 0.5*(1+erf((x-mu)/(sigma*sqrt(2))))
    const float mu  = 0.707107f;
    const float inv = 1.0f / (0.282095f * 1.41421356237f);
    return 0.5f * (1.0f + erff((x - mu) * inv));
}

// ------------------------------ layernorm -----------------------------------
__global__ void ln_kernel(const float* __restrict__ x,
                          const float* __restrict__ w,
                          const float* __restrict__ bb) {
    int row = blockIdx.x;                       // row = l*BATCH + b
    const float4* xr = (const float4*)(x + (size_t)row * DDIM);
    float4 v = xr[threadIdx.x];                 // 256 threads * 4 = 1024
    float s  = v.x + v.y + v.z + v.w;
    float s2 = v.x * v.x + v.y * v.y + v.z * v.z + v.w * v.w;
    #pragma unroll
    for (int o = 16; o; o >>= 1) {
        s  += __shfl_xor_sync(0xffffffffu, s, o);
        s2 += __shfl_xor_sync(0xffffffffu, s2, o);
    }
    __shared__ float sm[8], sm2[8];
    int wid = threadIdx.x >> 5, lid = threadIdx.x & 31;
    if (!lid) { sm[wid] = s; sm2[wid] = s2; }
    __syncthreads();
    if (threadIdx.x < 32) {
        s  = (threadIdx.x < 8) ? sm [threadIdx.x] : 0.f;
        s2 = (threadIdx.x < 8) ? sm2[threadIdx.x] : 0.f;
        #pragma unroll
        for (int o = 4; o; o >>= 1) {
            s  += __shfl_xor_sync(0xffffffffu, s, o);
            s2 += __shfl_xor_sync(0xffffffffu, s2, o);
        }
        if (!threadIdx.x) { sm[0] = s; sm2[0] = s2; }
    }
    __syncthreads();
    float mean = sm[0] * (1.f / DDIM);
    float var  = sm2[0] * (1.f / DDIM) - mean * mean;
    float rstd = rsqrtf(var + 1e-5f);
    int c = threadIdx.x * 4;
    float4 o4;
    o4.x = (v.x - mean) * rstd * w[c + 0] + bb[c + 0];
    o4.y = (v.y - mean) * rstd * w[c + 1] + bb[c + 1];
    o4.z = (v.z - mean) * rstd * w[c + 2] + bb[c + 2];
    o4.w = (v.w - mean) * rstd * w[c + 3] + bb[c + 3];
    ((float4*)(g_xn + (size_t)row * DDIM))[threadIdx.x] = o4;
}

// --------------------------- EMA coefficients --------------------------------
__global__ void ema_coef_kernel(const float* __restrict__ delta,
                                const float* __restrict__ alpha,
                                const float* __restrict__ beta,
                                const float* __restrict__ gamma) {
    int i = blockIdx.x * 256 + threadIdx.x;     // i < D*NEMA
    float p = sigmoidf_(delta[i]);
    float q = 1.f - p * sigmoidf_(alpha[i]);
    g_qn[i] = q;
    g_wn[i] = p * beta[i] * gamma[i] * 0.25f;   // scale = 1/sqrt(16)
}

// ------------------------------ EMA scan -------------------------------------
// out[l] = silu( sum_n w_n * s_n[l] + omega*x[l] ),  s_n[l] = q_n s_n[l-1] + x[l]
__global__ void ema_scan_kernel(const float* __restrict__ omega) {
    int t = blockIdx.x * blockDim.x + threadIdx.x;  // 0..8191
    int b = t / DDIM, d = t % DDIM;
    float q[NEMA], w[NEMA], s[NEMA];
    #pragma unroll
    for (int n = 0; n < NEMA; n++) {
        q[n] = g_qn[d * NEMA + n];
        w[n] = g_wn[d * NEMA + n];
        s[n] = 0.f;
    }
    float om = omega[d];
    size_t idx = (size_t)b * DDIM + d;
    for (int l = 0; l < LSEQ; l++) {
        float xv = g_xn[idx];
        float a0 = 0.f, a1 = 0.f, a2 = 0.f, a3 = 0.f;
        #pragma unroll
        for (int n = 0; n < NEMA; n += 4) {
            s[n + 0] = q[n + 0] * s[n + 0] + xv;  a0 += w[n + 0] * s[n + 0];
            s[n + 1] = q[n + 1] * s[n + 1] + xv;  a1 += w[n + 1] * s[n + 1];
            s[n + 2] = q[n + 2] * s[n + 2] + xv;  a2 += w[n + 2] * s[n + 2];
            s[n + 3] = q[n + 3] * s[n + 3] + xv;  a3 += w[n + 3] * s[n + 3];
        }
        g_mx[idx] = siluf_((a0 + a1) + (a2 + a3) + om * xv);
        idx += (size_t)BATCH * DDIM;
    }
}

// ------------------------------- GEMM ----------------------------------------
// Generic fp32 tiled GEMM, 128x128x16 tiles, 256 threads, 8x8 per thread.
// MODE 0: v     = silu(xn @ v_w + v_b)                -> g_v   (b,l,h)
// MODE 1: base  = mx @ mx_w + mx_b, split epilogue    -> g_u, g_qm/g_kT, g_r, g_hx
// MODE 2: attn  = laplace(q @ kT / L + bias)          -> g_attn (per batch z)
// MODE 3: h     = (attn @ v) * r                      -> g_h   (per batch z)
// MODE 4: out   = x + u*(silu(hx + (g_h @ h_w) + h_b) - x)
template <int MODE>
__global__ void __launch_bounds__(256)
gemm_kernel(const float* __restrict__ Bext,
            const float* __restrict__ e0,
            const float* __restrict__ e1,
            float* __restrict__ outp) {
    constexpr int K  = (MODE == 0 || MODE == 1) ? DDIM
                     : (MODE == 2) ? ZDIM
                     : (MODE == 3) ? LSEQ : HDIM;
    constexpr int NC = (MODE == 0) ? HDIM
                     : (MODE == 1) ? DOUT
                     : (MODE == 2) ? LSEQ
                     : (MODE == 3) ? HDIM : DDIM;

    const float* Aab;
    const float* Bb;
    const int z = blockIdx.z;
    if constexpr (MODE == 0)      { Aab = g_xn;                              Bb = Bext; }
    else if constexpr (MODE == 1) { Aab = g_mx;                              Bb = Bext; }
    else if constexpr (MODE == 2) { Aab = g_qm + (size_t)z * LSEQ * ZDIM;    Bb = g_kT + (size_t)z * ZDIM * LSEQ; }
    else if constexpr (MODE == 3) { Aab = g_attn + (size_t)z * LSEQ * LSEQ;  Bb = g_v  + (size_t)z * LSEQ * HDIM; }
    else                          { Aab = g_h;                               Bb = Bext; }

    __shared__ float As[16][128];
    __shared__ float Bs[16][128];

    const int tid = threadIdx.x;
    const int tx = tid & 15, ty = tid >> 4;
    const int rowBase = blockIdx.y * 128;
    const int colBase = blockIdx.x * 128;

    const int arow = tid >> 2;          // 0..63
    const int acol = (tid & 3) * 4;     // 0,4,8,12
    const int brow = tid >> 5;          // 0..7
    const int bcol = (tid & 31) * 4;

    float acc[8][8];
    #pragma unroll
    for (int i = 0; i < 8; i++)
        #pragma unroll
        for (int j = 0; j < 8; j++) acc[i][j] = 0.f;

    for (int kt = 0; kt < K; kt += 16) {
        #pragma unroll
        for (int p = 0; p < 2; p++) {
            int r = arow + p * 64;
            float4 av = *(const float4*)(Aab + (size_t)(rowBase + r) * K + kt + acol);
            As[acol + 0][r] = av.x;
            As[acol + 1][r] = av.y;
            As[acol + 2][r] = av.z;
            As[acol + 3][r] = av.w;
        }
        #pragma unroll
        for (int p = 0; p < 2; p++) {
            int r = brow + p * 8;
            *(float4*)&Bs[r][bcol] =
                *(const float4*)(Bb + (size_t)(kt + r) * NC + colBase + bcol);
        }
        __syncthreads();
        #pragma unroll
        for (int k = 0; k < 16; k++) {
            float ra[8], rb[8];
            #pragma unroll
            for (int i = 0; i < 8; i++) ra[i] = As[k][ty * 8 + i];
            #pragma unroll
            for (int j = 0; j < 8; j++) rb[j] = Bs[k][tx * 8 + j];
            #pragma unroll
            for (int i = 0; i < 8; i++)
                #pragma unroll
                for (int j = 0; j < 8; j++) acc[i][j] += ra[i] * rb[j];
        }
        __syncthreads();
    }

    const int rowT = rowBase + ty * 8;
    const int colT = colBase + tx * 8;
    #pragma unroll
    for (int i = 0; i < 8; i++) {
        const int gr = rowT + i;
        #pragma unroll
        for (int j = 0; j < 8; j++) {
            const int gc = colT + j;
            float a = acc[i][j];
            if constexpr (MODE == 0) {
                int l = gr / BATCH, b = gr % BATCH;
                g_v[((size_t)b * LSEQ + l) * HDIM + gc] = siluf_(a + e0[gc]);
            } else if constexpr (MODE == 1) {
                float val = a + e0[gc];
                int l = gr / BATCH, b = gr % BATCH;
                if (gc < DDIM) {
                    g_u[(size_t)gr * DDIM + gc] = sigmoidf_(val);
                } else if (gc < DDIM + ZDIM) {
                    int zi = gc - DDIM;
                    float zz = siluf_(val);
                    g_qm[((size_t)b * LSEQ + l) * ZDIM + zi] = zz * e1[zi] + e1[2 * ZDIM + zi];
                    g_kT[((size_t)b * ZDIM + zi) * LSEQ + l] = zz * e1[ZDIM + zi] + e1[3 * ZDIM + zi];
                } else if (gc < DDIM + ZDIM + HDIM) {
                    int hi = gc - DDIM - ZDIM;
                    g_r[((size_t)b * LSEQ + l) * HDIM + hi] = siluf_(val);
                } else {
                    int di = gc - (DDIM + ZDIM + HDIM);
                    g_hx[(size_t)gr * DDIM + di] = val;
                }
            } else if constexpr (MODE == 2) {
                float s = a * (1.0f / (float)LSEQ) + e0[MAXPOS - 1 + gc - gr];
                g_attn[((size_t)z * LSEQ + gr) * LSEQ + gc] = laplacef_(s);
            } else if constexpr (MODE == 3) {
                size_t o = ((size_t)z * LSEQ + gr) * HDIM + gc;
                g_h[o] = a * g_r[o];
            } else {  // MODE 4
                int b = gr / LSEQ, l = gr % LSEQ;
                size_t o = (size_t)(l * BATCH + b) * DDIM + gc;
                float hval = siluf_(g_hx[o] + a + e0[gc]);
                float xv = e1[o];
                float uu = g_u[o];
                outp[o] = xv + uu * (hval - xv);
            }
        }
    }
}

// For MODE 1: qk_gamma (2,Z) and qk_beta (2,Z) packed into one 4*Z buffer.
__device__ float g_qkgb[4 * ZDIM];
__global__ void pack_qkgb_kernel(const float* __restrict__ qk_gamma,
                                 const float* __restrict__ qk_beta) {
    int i = threadIdx.x + blockIdx.x * 256;
    if (i < 2 * ZDIM) {
        g_qkgb[i] = qk_gamma[i];
        g_qkgb[2 * ZDIM + i] = qk_beta[i];
    }
}
// Device symbol address helper: we can't take &g_qkgb on host without API
// calls, so MODE 1 reads the packed buffer through a device-side pointer.
// Simpler: pass qk_gamma/qk_beta via a tiny trampoline. Instead MODE 1's e1
// points at g_qkgb via a dedicated launch wrapper below.
__global__ void gemm_mode1_wrapper_dummy() {}

// ----------------------------------------------------------------------------
extern "C" void kernel_launch(void* const* d_in, const int* in_sizes, int n_in,
                              void* d_out, int out_size) {
    const float* x        = (const float*)d_in[0];
    const float* delta    = (const float*)d_in[1];
    const float* alpha    = (const float*)d_in[2];
    const float* beta_ema = (const float*)d_in[3];
    const float* gamma_em = (const float*)d_in[4];
    const float* omega    = (const float*)d_in[5];
    const float* v_w      = (const float*)d_in[6];
    const float* v_b      = (const float*)d_in[7];
    const float* mx_w     = (const float*)d_in[8];
    const float* mx_b     = (const float*)d_in[9];
    const float* h_w      = (const float*)d_in[10];
    const float* h_b      = (const float*)d_in[11];
    const float* qk_gamma = (const float*)d_in[12];
    const float* qk_beta  = (const float*)d_in[13];
    const float* rel_pos  = (const float*)d_in[14];
    const float* ln_w     = (const float*)d_in[15];
    const float* ln_b     = (const float*)d_in[16];
    float* out = (float*)d_out;

    // 1) layernorm
    ln_kernel<<<LSEQ * BATCH, 256>>>(x, ln_w, ln_b);

    // 2) ema coefficients + scan + silu
    ema_coef_kernel<<<(DDIM * NEMA) / 256, 256>>>(delta, alpha, beta_ema, gamma_em);
    ema_scan_kernel<<<(BATCH * DDIM) / 256, 256>>>(omega);

    // pack qk gamma/beta into one device buffer for the MODE 1 epilogue
    pack_qkgb_kernel<<<1, 256>>>(qk_gamma, qk_beta);

    // 3) v = silu(xn @ v_w + v_b)
    gemm_kernel<0><<<dim3(HDIM / 128, (LSEQ * BATCH) / 128, 1), 256>>>(v_w, v_b, nullptr, nullptr);

    // 4) base = mx @ mx_w + mx_b (u / q,kT / r / hx epilogue)
    {
        // e1 must point at g_qkgb; obtain its device address once via a
        // device-symbol lookup. cudaGetSymbolAddress performs no stream work
        // and no allocation, so it is graph-capture safe.
        static float* qkgb_dev = nullptr;
        if (!qkgb_dev) cudaGetSymbolAddress((void**)&qkgb_dev, g_qkgb);
        gemm_kernel<1><<<dim3(DOUT / 128, (LSEQ * BATCH) / 128, 1), 256>>>(mx_w, mx_b, qkgb_dev, nullptr);
    }

    // 5) attn = laplace(q @ kT / L + relbias)   (per batch)
    gemm_kernel<2><<<dim3(LSEQ / 128, LSEQ / 128, BATCH), 256>>>(nullptr, rel_pos, nullptr, nullptr);

    // 6) h = (attn @ v) * r                     (per batch)
    gemm_kernel<3><<<dim3(HDIM / 128, LSEQ / 128, BATCH), 256>>>(nullptr, nullptr, nullptr, nullptr);

    // 7) out = x + u * (silu(hx + (h @ h_w) + h_b) - x)
    gemm_kernel<4><<<dim3(DDIM / 128, (LSEQ * BATCH) / 128, 1), 256>>>(h_w, h_b, x, out);
}

// round 4
// speedup vs baseline: 6.0298x; 6.0298x over previous
#include <cuda_runtime.h>
#include <cuda_fp16.h>
#include <math.h>
#include <cstdint>

// ---------------------------------------------------------------------------
// MEGA forward, mma.sync fp16 GEMMs (base sm_100 tensor path).
// L=2048 B=8 D=1024 Z=128 H=2048 N=16
// ---------------------------------------------------------------------------

#define LSEQ   2048
#define BATCH  8
#define DDIM   1024
#define ZDIM   128
#define HDIM   2048
#define NEMA   16
#define MAXPOS 2048
#define DOUT   (ZDIM + HDIM + 2 * DDIM)   // 4224
#define NCH    8
#define CHL    (LSEQ / NCH)               // 256

// ------------------------- scratch (device globals) ------------------------
__device__ float  g_xn  [LSEQ * BATCH * DDIM];            // fp32 for EMA scan
__device__ float  g_u   [LSEQ * BATCH * DDIM];
__device__ float  g_hx  [LSEQ * BATCH * DDIM];
__device__ float  g_r   [(size_t)BATCH * LSEQ * HDIM];
__device__ __half xn16  [LSEQ * BATCH * DDIM];            // (l*B+b, d)
__device__ __half mx16  [LSEQ * BATCH * DDIM];
__device__ __half v16   [(size_t)BATCH * LSEQ * HDIM];    // (b,l,h)
__device__ __half vT16  [(size_t)BATCH * HDIM * LSEQ];    // (b,h,l)
__device__ __half h16   [(size_t)BATCH * LSEQ * HDIM];    // (b*L+l, h)
__device__ __half q16   [BATCH * LSEQ * ZDIM];
__device__ __half k16   [BATCH * LSEQ * ZDIM];
__device__ __half attn16[(size_t)BATCH * LSEQ * LSEQ];    // (b,l,m)
__device__ __half w_v16 [HDIM * DDIM];                    // v_w^T  (h,d)
__device__ __half w_mx16[(size_t)DOUT * DDIM];            // mx_w^T (n,d)
__device__ __half w_h16 [DDIM * HDIM];                    // h_w^T  (d,h)
__device__ float  g_wn  [DDIM * NEMA];
__device__ float  g_qn  [DDIM * NEMA];
__device__ float  g_qp  [DDIM * NEMA];
__device__ float  g_send [BATCH * NCH * DDIM * NEMA];
__device__ float  g_carry[BATCH * NCH * DDIM * NEMA];

// ------------------------------- ptx helpers --------------------------------
__device__ __forceinline__ uint32_t smem_u32(const void* p) {
    uint32_t a;
    asm("{ .reg .u64 t; cvta.to.shared.u64 t, %1; cvt.u32.u64 %0, t; }" : "=r"(a) : "l"(p));
    return a;
}
#define CP16(dst, src) \
    asm volatile("cp.async.cg.shared.global [%0], [%1], 16;" :: "r"(dst), "l"(src))
#define CP_COMMIT() asm volatile("cp.async.commit_group;" ::: "memory")
#define CP_WAIT(n)  asm volatile("cp.async.wait_group %0;" :: "n"(n) : "memory")

__device__ __forceinline__ void ldsm4(uint32_t& r0, uint32_t& r1, uint32_t& r2,
                                      uint32_t& r3, uint32_t addr) {
    asm volatile("ldmatrix.sync.aligned.m8n8.x4.shared.b16 {%0,%1,%2,%3}, [%4];"
                 : "=r"(r0), "=r"(r1), "=r"(r2), "=r"(r3) : "r"(addr));
}
__device__ __forceinline__ void mma16816(float* d, const uint32_t* a,
                                         uint32_t b0, uint32_t b1) {
    asm volatile(
        "mma.sync.aligned.m16n8k16.row.col.f32.f16.f16.f32 "
        "{%0,%1,%2,%3}, {%4,%5,%6,%7}, {%8,%9}, {%0,%1,%2,%3};"
        : "+f"(d[0]), "+f"(d[1]), "+f"(d[2]), "+f"(d[3])
        : "r"(a[0]), "r"(a[1]), "r"(a[2]), "r"(a[3]), "r"(b0), "r"(b1));
}
__device__ __forceinline__ uint32_t swz(int row, int c) {
    return (uint32_t)(row * 64 + ((c ^ ((row >> 1) & 3)) << 4));
}

// ------------------------------- math helpers --------------------------------
__device__ __forceinline__ float sigmoidf_(float x) { return 1.f / (1.f + __expf(-x)); }
__device__ __forceinline__ float siluf_(float x)    { return x / (1.f + __expf(-x)); }
__device__ __forceinline__ float laplacef_(float x) {
    const float mu  = 0.707107f;
    const float inv = 1.0f / (0.282095f * 1.41421356237f);
    return 0.5f * (1.0f + erff((x - mu) * inv));
}

// ------------------------------ layernorm ------------------------------------
__global__ void ln_kernel(const float* __restrict__ x,
                          const float* __restrict__ w,
                          const float* __restrict__ bb) {
    int row = blockIdx.x;
    const float4* xr = (const float4*)(x + (size_t)row * DDIM);
    float4 v = xr[threadIdx.x];
    float s  = v.x + v.y + v.z + v.w;
    float s2 = v.x * v.x + v.y * v.y + v.z * v.z + v.w * v.w;
    #pragma unroll
    for (int o = 16; o; o >>= 1) {
        s  += __shfl_xor_sync(0xffffffffu, s, o);
        s2 += __shfl_xor_sync(0xffffffffu, s2, o);
    }
    __shared__ float sm[8], sm2[8];
    int wid = threadIdx.x >> 5, lid = threadIdx.x & 31;
    if (!lid) { sm[wid] = s; sm2[wid] = s2; }
    __syncthreads();
    if (threadIdx.x < 32) {
        s  = (threadIdx.x < 8) ? sm [threadIdx.x] : 0.f;
        s2 = (threadIdx.x < 8) ? sm2[threadIdx.x] : 0.f;
        #pragma unroll
        for (int o = 4; o; o >>= 1) {
            s  += __shfl_xor_sync(0xffffffffu, s, o);
            s2 += __shfl_xor_sync(0xffffffffu, s2, o);
        }
        if (!threadIdx.x) { sm[0] = s; sm2[0] = s2; }
    }
    __syncthreads();
    float mean = sm[0] * (1.f / DDIM);
    float var  = sm2[0] * (1.f / DDIM) - mean * mean;
    float rstd = rsqrtf(var + 1e-5f);
    int c = threadIdx.x * 4;
    float4 o4;
    o4.x = (v.x - mean) * rstd * w[c + 0] + bb[c + 0];
    o4.y = (v.y - mean) * rstd * w[c + 1] + bb[c + 1];
    o4.z = (v.z - mean) * rstd * w[c + 2] + bb[c + 2];
    o4.w = (v.w - mean) * rstd * w[c + 3] + bb[c + 3];
    size_t o = (size_t)row * DDIM + c;
    ((float4*)(g_xn + (size_t)row * DDIM))[threadIdx.x] = o4;
    *(__half2*)(xn16 + o)     = __floats2half2_rn(o4.x, o4.y);
    *(__half2*)(xn16 + o + 2) = __floats2half2_rn(o4.z, o4.w);
}

// --------------------------- EMA coefficients --------------------------------
__global__ void ema_coef_kernel(const float* __restrict__ delta,
                                const float* __restrict__ alpha,
                                const float* __restrict__ beta,
                                const float* __restrict__ gamma) {
    int i = blockIdx.x * 256 + threadIdx.x;
    float p = sigmoidf_(delta[i]);
    float q = 1.f - p * sigmoidf_(alpha[i]);
    g_qn[i] = q;
    g_wn[i] = p * beta[i] * gamma[i] * 0.25f;
    float qp = q;
    #pragma unroll
    for (int k = 0; k < 8; k++) qp *= qp;   // q^256
    g_qp[i] = qp;
}

// ---------------------------- EMA 3-phase scan --------------------------------
__global__ void ema_scanA() {
    int idx = blockIdx.x * 256 + threadIdx.x;       // 65536 total
    int d = idx & (DDIM - 1);
    int t = idx >> 10;
    int b = t & 7, c = t >> 3;
    float q[NEMA], s[NEMA];
    #pragma unroll
    for (int n = 0; n < NEMA; n++) { q[n] = g_qn[d * NEMA + n]; s[n] = 0.f; }
    size_t xi = ((size_t)(c * CHL) * BATCH + b) * DDIM + d;
    for (int l = 0; l < CHL; l++) {
        float xv = g_xn[xi];
        #pragma unroll
        for (int n = 0; n < NEMA; n++) s[n] = q[n] * s[n] + xv;
        xi += (size_t)BATCH * DDIM;
    }
    float* dst = g_send + ((size_t)(b * NCH + c) * DDIM + d) * NEMA;
    #pragma unroll
    for (int n = 0; n < NEMA; n++) dst[n] = s[n];
}

__global__ void ema_scanB() {
    int idx = blockIdx.x * 256 + threadIdx.x;       // 8192 total
    int d = idx & (DDIM - 1);
    int b = idx >> 10;
    float carry[NEMA], qp[NEMA];
    #pragma unroll
    for (int n = 0; n < NEMA; n++) { carry[n] = 0.f; qp[n] = g_qp[d * NEMA + n]; }
    for (int c = 0; c < NCH; c++) {
        float* cd = g_carry + ((size_t)(b * NCH + c) * DDIM + d) * NEMA;
        const float* sd = g_send + ((size_t)(b * NCH + c) * DDIM + d) * NEMA;
        #pragma unroll
        for (int n = 0; n < NEMA; n++) {
            cd[n] = carry[n];
            carry[n] = qp[n] * carry[n] + sd[n];
        }
    }
}

__global__ void ema_scanC(const float* __restrict__ omega) {
    int idx = blockIdx.x * 256 + threadIdx.x;
    int d = idx & (DDIM - 1);
    int t = idx >> 10;
    int b = t & 7, c = t >> 3;
    float q[NEMA], w[NEMA], s[NEMA];
    const float* cd = g_carry + ((size_t)(b * NCH + c) * DDIM + d) * NEMA;
    #pragma unroll
    for (int n = 0; n < NEMA; n++) {
        q[n] = g_qn[d * NEMA + n];
        w[n] = g_wn[d * NEMA + n];
        s[n] = cd[n];
    }
    float om = omega[d];
    size_t xi = ((size_t)(c * CHL) * BATCH + b) * DDIM + d;
    for (int l = 0; l < CHL; l++) {
        float xv = g_xn[xi];
        float a0 = 0.f, a1 = 0.f;
        #pragma unroll
        for (int n = 0; n < NEMA; n += 2) {
            s[n]     = q[n]     * s[n]     + xv;  a0 += w[n]     * s[n];
            s[n + 1] = q[n + 1] * s[n + 1] + xv;  a1 += w[n + 1] * s[n + 1];
        }
        mx16[xi] = __float2half(siluf_(a0 + a1 + om * xv));
        xi += (size_t)BATCH * DDIM;
    }
}

// ------------------------------ transposes -----------------------------------
// weights fp32 -> fp16 transposed
template <int WHICH>
__global__ void transpose_w(const float* __restrict__ in, int R, int C) {
    __shared__ float t[32][33];
    __half* op = (WHICH == 0) ? w_v16 : (WHICH == 1) ? w_mx16 : w_h16;
    int c0 = blockIdx.x * 32, r0 = blockIdx.y * 32;
    int tx = threadIdx.x, ty = threadIdx.y;
    #pragma unroll
    for (int k = 0; k < 4; k++)
        t[ty + 8 * k][tx] = in[(size_t)(r0 + ty + 8 * k) * C + c0 + tx];
    __syncthreads();
    #pragma unroll
    for (int k = 0; k < 4; k++)
        op[(size_t)(c0 + ty + 8 * k) * R + r0 + tx] = __float2half(t[tx][ty + 8 * k]);
}

// v16 (b,l,h) -> vT16 (b,h,l), fp16
__global__ void transpose_v16() {
    __shared__ __half t[32][36];
    const __half* ip = v16 + (size_t)blockIdx.z * LSEQ * HDIM;
    __half* op = vT16 + (size_t)blockIdx.z * (size_t)HDIM * LSEQ;
    int c0 = blockIdx.x * 32, r0 = blockIdx.y * 32;
    int tx = threadIdx.x, ty = threadIdx.y;
    #pragma unroll
    for (int k = 0; k < 4; k++)
        t[ty + 8 * k][tx] = ip[(size_t)(r0 + ty + 8 * k) * HDIM + c0 + tx];
    __syncthreads();
    #pragma unroll
    for (int k = 0; k < 4; k++)
        op[(size_t)(c0 + ty + 8 * k) * LSEQ + r0 + tx] = t[tx][ty + 8 * k];
}

// --------------------------- fp16 mma.sync GEMM ------------------------------
// MODE 0: v16   = silu(xn16 @ w_v16^T + v_b)          K=1024
// MODE 1: base  = mx16 @ w_mx16^T + mx_b (split epi)  K=1024
// MODE 2: attn16= laplace(q16 @ k16^T / L + bias)     K=128
// MODE 3: h16   = (attn16 @ vT16^T) * r               K=2048
// MODE 4: out   = x + u*(silu(hx + h16@w_h16^T+h_b)-x) K=2048
#define SMEM_BYTES (128 * 132 * 4)   // 67584; mainloop needs 3*16384=49152

template <int MODE>
__global__ void __launch_bounds__(256)
hgemm(const float* __restrict__ bias,
      const float* __restrict__ ex0,
      const float* __restrict__ ex1,
      float* __restrict__ outp) {
    constexpr int K = (MODE == 0 || MODE == 1) ? 1024 : (MODE == 2) ? 128 : 2048;
    constexpr int NK = K / 32;
    constexpr int STAGES = 3;

    extern __shared__ char smem[];
    const uint32_t sb = smem_u32(smem);
    const int tid = threadIdx.x, lane = tid & 31, wid = tid >> 5;
    const int wm = wid >> 2, wn = wid & 3;
    const int z = blockIdx.z;
    const int rowBase = blockIdx.y * 128;
    const int colBase = blockIdx.x * 128;

    const __half* A; const __half* Bp;
    if constexpr (MODE == 0)      { A = xn16;  Bp = w_v16; }
    else if constexpr (MODE == 1) { A = mx16;  Bp = w_mx16; }
    else if constexpr (MODE == 2) { A = q16 + (size_t)z * LSEQ * ZDIM;
                                    Bp = k16 + (size_t)z * LSEQ * ZDIM; }
    else if constexpr (MODE == 3) { A = attn16 + (size_t)z * LSEQ * LSEQ;
                                    Bp = vT16 + (size_t)z * (size_t)HDIM * LSEQ; }
    else                          { A = h16;   Bp = w_h16; }

    // cp.async mapping: 512 16B-elems per tile, 2 per thread
    const int e0r = tid >> 2,          e0c = tid & 3;
    const int e1r = (tid + 256) >> 2;  // e1c == e0c

    float acc[4][4][4];
    #pragma unroll
    for (int mi = 0; mi < 4; mi++)
        #pragma unroll
        for (int ni = 0; ni < 4; ni++)
            #pragma unroll
            for (int j = 0; j < 4; j++) acc[mi][ni][j] = 0.f;

    auto load_stage = [&](int i) {
        const int kt = i * 32;
        const uint32_t as = sb + (i % STAGES) * 16384u;
        const uint32_t bs = as + 8192u;
        CP16(as + swz(e0r, e0c), A  + (size_t)(rowBase + e0r) * K + kt + e0c * 8);
        CP16(as + swz(e1r, e0c), A  + (size_t)(rowBase + e1r) * K + kt + e0c * 8);
        CP16(bs + swz(e0r, e0c), Bp + (size_t)(colBase + e0r) * K + kt + e0c * 8);
        CP16(bs + swz(e1r, e0c), Bp + (size_t)(colBase + e1r) * K + kt + e0c * 8);
    };

    #pragma unroll
    for (int s = 0; s < STAGES - 1; s++) {
        if (s < NK) load_stage(s);
        CP_COMMIT();
    }

    for (int i = 0; i < NK; i++) {
        CP_WAIT(STAGES - 2);
        __syncthreads();
        const uint32_t as = sb + (i % STAGES) * 16384u;
        const uint32_t bs = as + 8192u;
        #pragma unroll
        for (int kk = 0; kk < 2; kk++) {
            uint32_t a[4][4], b[4][2];
            const int arow = wm * 64 + (lane & 15);
            const int achunk = kk * 2 + (lane >> 4);
            #pragma unroll
            for (int mi = 0; mi < 4; mi++)
                ldsm4(a[mi][0], a[mi][1], a[mi][2], a[mi][3],
                      as + swz(arow + mi * 16, achunk));
            const int brow = wn * 32 + (lane & 7) + ((lane >> 4) << 3);
            const int bchunk = kk * 2 + ((lane >> 3) & 1);
            #pragma unroll
            for (int nb = 0; nb < 2; nb++)
                ldsm4(b[2 * nb][0], b[2 * nb][1], b[2 * nb + 1][0], b[2 * nb + 1][1],
                      bs + swz(brow + nb * 16, bchunk));
            #pragma unroll
            for (int mi = 0; mi < 4; mi++)
                #pragma unroll
                for (int ni = 0; ni < 4; ni++)
                    mma16816(acc[mi][ni], a[mi], b[ni][0], b[ni][1]);
        }
        if (i + STAGES - 1 < NK) load_stage(i + STAGES - 1);
        CP_COMMIT();
    }
    CP_WAIT(0);
    __syncthreads();

    // phase 1: accum regs -> smem fp32 tile (pitch 132)
    float* tile = (float*)smem;
    #pragma unroll
    for (int mi = 0; mi < 4; mi++)
        #pragma unroll
        for (int ni = 0; ni < 4; ni++) {
            int r0 = wm * 64 + mi * 16 + (lane >> 2);
            int c  = wn * 32 + ni * 8 + (lane & 3) * 2;
            *(float2*)&tile[r0 * 132 + c]       = make_float2(acc[mi][ni][0], acc[mi][ni][1]);
            *(float2*)&tile[(r0 + 8) * 132 + c] = make_float2(acc[mi][ni][2], acc[mi][ni][3]);
        }
    __syncthreads();

    // phase 2: coalesced epilogue
    #pragma unroll 1
    for (int p = 0; p < 16; p++) {
        int linear = p * 256 + tid;
        int rr = linear >> 5;
        int c4 = (linear & 31) * 4;
        float4 v4 = *(float4*)&tile[rr * 132 + c4];
        float vals[4] = {v4.x, v4.y, v4.z, v4.w};
        const int gr = rowBase + rr;
        const int gc0 = colBase + c4;

        if constexpr (MODE == 0) {
            int l = gr / BATCH, b = gr % BATCH;
            size_t o = ((size_t)b * LSEQ + l) * HDIM + gc0;
            __half2 p0 = __floats2half2_rn(siluf_(vals[0] + bias[gc0 + 0]),
                                           siluf_(vals[1] + bias[gc0 + 1]));
            __half2 p1 = __floats2half2_rn(siluf_(vals[2] + bias[gc0 + 2]),
                                           siluf_(vals[3] + bias[gc0 + 3]));
            *(__half2*)(v16 + o)     = p0;
            *(__half2*)(v16 + o + 2) = p1;
        } else if constexpr (MODE == 1) {
            int l = gr / BATCH, b = gr % BATCH;
            #pragma unroll
            for (int q4 = 0; q4 < 4; q4++) {
                int gc = gc0 + q4;
                float val = vals[q4] + bias[gc];
                if (gc < DDIM) {
                    g_u[(size_t)gr * DDIM + gc] = sigmoidf_(val);
                } else if (gc < DDIM + ZDIM) {
                    int zi = gc - DDIM;
                    float zz = siluf_(val);
                    size_t qo = ((size_t)b * LSEQ + l) * ZDIM + zi;
                    q16[qo] = __float2half(zz * ex0[zi]        + ex1[zi]);
                    k16[qo] = __float2half(zz * ex0[ZDIM + zi] + ex1[ZDIM + zi]);
                } else if (gc < DDIM + ZDIM + HDIM) {
                    int hi = gc - DDIM - ZDIM;
                    g_r[((size_t)b * LSEQ + l) * HDIM + hi] = siluf_(val);
                } else {
                    int di = gc - (DDIM + ZDIM + HDIM);
                    g_hx[(size_t)gr * DDIM + di] = val;
                }
            }
        } else if constexpr (MODE == 2) {
            size_t o = ((size_t)z * LSEQ + gr) * LSEQ + gc0;
            __half2 p0 = __floats2half2_rn(
                laplacef_(vals[0] * (1.f / LSEQ) + ex0[MAXPOS - 1 + gc0 + 0 - gr]),
                laplacef_(vals[1] * (1.f / LSEQ) + ex0[MAXPOS - 1 + gc0 + 1 - gr]));
            __half2 p1 = __floats2half2_rn(
                laplacef_(vals[2] * (1.f / LSEQ) + ex0[MAXPOS - 1 + gc0 + 2 - gr]),
                laplacef_(vals[3] * (1.f / LSEQ) + ex0[MAXPOS - 1 + gc0 + 3 - gr]));
            *(__half2*)(attn16 + o)     = p0;
            *(__half2*)(attn16 + o + 2) = p1;
        } else if constexpr (MODE == 3) {
            size_t o = ((size_t)z * LSEQ + gr) * HDIM + gc0;
            float4 rv = *(const float4*)(g_r + o);
            __half2 p0 = __floats2half2_rn(vals[0] * rv.x, vals[1] * rv.y);
            __half2 p1 = __floats2half2_rn(vals[2] * rv.z, vals[3] * rv.w);
            *(__half2*)(h16 + o)     = p0;
            *(__half2*)(h16 + o + 2) = p1;
        } else {  // MODE 4
            int b = gr >> 11, l = gr & (LSEQ - 1);
            size_t o = (size_t)(l * BATCH + b) * DDIM + gc0;
            float4 hx4 = *(const float4*)(g_hx + o);
            float4 u4  = *(const float4*)(g_u + o);
            float4 x4  = *(const float4*)(ex1 + o);
            float4 w4;
            w4.x = x4.x + u4.x * (siluf_(hx4.x + vals[0] + bias[gc0 + 0]) - x4.x);
            w4.y = x4.y + u4.y * (siluf_(hx4.y + vals[1] + bias[gc0 + 1]) - x4.y);
            w4.z = x4.z + u4.z * (siluf_(hx4.z + vals[2] + bias[gc0 + 2]) - x4.z);
            w4.w = x4.w + u4.w * (siluf_(hx4.w + vals[3] + bias[gc0 + 3]) - x4.w);
            *(float4*)(outp + o) = w4;
        }
    }
}

// ----------------------------------------------------------------------------
extern "C" void kernel_launch(void* const* d_in, const int* in_sizes, int n_in,
                              void* d_out, int out_size) {
    const float* x        = (const float*)d_in[0];
    const float* delta    = (const float*)d_in[1];
    const float* alpha    = (const float*)d_in[2];
    const float* beta_ema = (const float*)d_in[3];
    const float* gamma_em = (const float*)d_in[4];
    const float* omega    = (const float*)d_in[5];
    const float* v_w      = (const float*)d_in[6];
    const float* v_b      = (const float*)d_in[7];
    const float* mx_w     = (const float*)d_in[8];
    const float* mx_b     = (const float*)d_in[9];
    const float* h_w      = (const float*)d_in[10];
    const float* h_b      = (const float*)d_in[11];
    const float* qk_gamma = (const float*)d_in[12];
    const float* qk_beta  = (const float*)d_in[13];
    const float* rel_pos  = (const float*)d_in[14];
    const float* ln_w     = (const float*)d_in[15];
    const float* ln_b     = (const float*)d_in[16];
    float* out = (float*)d_out;

    cudaFuncSetAttribute(hgemm<0>, cudaFuncAttributeMaxDynamicSharedMemorySize, SMEM_BYTES);
    cudaFuncSetAttribute(hgemm<1>, cudaFuncAttributeMaxDynamicSharedMemorySize, SMEM_BYTES);
    cudaFuncSetAttribute(hgemm<2>, cudaFuncAttributeMaxDynamicSharedMemorySize, SMEM_BYTES);
    cudaFuncSetAttribute(hgemm<3>, cudaFuncAttributeMaxDynamicSharedMemorySize, SMEM_BYTES);
    cudaFuncSetAttribute(hgemm<4>, cudaFuncAttributeMaxDynamicSharedMemorySize, SMEM_BYTES);

    dim3 tblk(32, 8);

    // weight transposes (fp32 -> fp16, independent)
    transpose_w<0><<<dim3(HDIM / 32, DDIM / 32, 1), tblk>>>(v_w, DDIM, HDIM);
    transpose_w<1><<<dim3(DOUT / 32, DDIM / 32, 1), tblk>>>(mx_w, DDIM, DOUT);
    transpose_w<2><<<dim3(DDIM / 32, HDIM / 32, 1), tblk>>>(h_w, HDIM, DDIM);

    // layernorm + EMA
    ln_kernel<<<LSEQ * BATCH, 256>>>(x, ln_w, ln_b);
    ema_coef_kernel<<<(DDIM * NEMA) / 256, 256>>>(delta, alpha, beta_ema, gamma_em);
    ema_scanA<<<(BATCH * DDIM * NCH) / 256, 256>>>();
    ema_scanB<<<(BATCH * DDIM) / 256, 256>>>();
    ema_scanC<<<(BATCH * DDIM * NCH) / 256, 256>>>(omega);

    // v = silu(xn @ v_w + v_b)
    hgemm<0><<<dim3(HDIM / 128, (LSEQ * BATCH) / 128, 1), 256, SMEM_BYTES>>>(
        v_b, nullptr, nullptr, nullptr);
    transpose_v16<<<dim3(HDIM / 32, LSEQ / 32, BATCH), tblk>>>();

    // base = mx @ mx_w + mx_b with split epilogue
    hgemm<1><<<dim3(DOUT / 128, (LSEQ * BATCH) / 128, 1), 256, SMEM_BYTES>>>(
        mx_b, qk_gamma, qk_beta, nullptr);

    // attn = laplace(q @ k^T / L + bias)
    hgemm<2><<<dim3(LSEQ / 128, LSEQ / 128, BATCH), 256, SMEM_BYTES>>>(
        nullptr, rel_pos, nullptr, nullptr);

    // h = (attn @ v) * r
    hgemm<3><<<dim3(HDIM / 128, LSEQ / 128, BATCH), 256, SMEM_BYTES>>>(
        nullptr, nullptr, nullptr, nullptr);

    // out = x + u * (silu(hx + h @ h_w + h_b) - x)
    hgemm<4><<<dim3(DDIM / 128, (LSEQ * BATCH) / 128, 1), 256, SMEM_BYTES>>>(
        h_b, nullptr, x, out);
}